// round 9
// baseline (speedup 1.0000x reference)
#include <cuda_runtime.h>

// Problem constants
#define NK 16384                 // finest block size N[2]
#define KB 32                    // k's per block
#define A_ELEMS (21*21*NK)       // 7225344 per (re/im) plane
#define LOGDET_OFF (2*A_ELEMS)   // 14450688
#define ZOUT_OFF (LOGDET_OFF+1)
#define ZTOT (21*NK)             // 344064

// ---- scratch (L2-resident), ~9.2 MB ----
__device__ float g_T1r[4*4*NK], g_T1i[4*4*NK];   // [j][b][k]
__device__ float g_P1r[4*4*NK], g_P1i[4*4*NK];   // [j][a][k]
__device__ float g_A0r[4*4*NK], g_A0i[4*4*NK];   // [j][j0][k]
__device__ float g_S1r[4*NK],   g_S1i[4*NK];     // 1/S1 [j][k]
__device__ float g_T2r[20*NK],  g_T2i[20*NK];    // [p][k]
__device__ float g_S2r[NK],     g_S2i[NK];       // 1/S2 [k]

__global__ void _fmgp_zero_logdet(float* out){ out[LOGDET_OFF] = 0.0f; }

// ================= K1: factor (phases A + B + S2 + logdet) =================
__global__ __launch_bounds__(320, 4)
void _fmgp_k1(const float* __restrict__ l00r, const float* __restrict__ l00i,
              const float* __restrict__ l01r, const float* __restrict__ l01i,
              const float* __restrict__ l02r, const float* __restrict__ l02i,
              const float* __restrict__ l11r, const float* __restrict__ l11i,
              const float* __restrict__ l12r, const float* __restrict__ l12i,
              const float* __restrict__ l22r, const float* __restrict__ l22i,
              float* __restrict__ out)
{
    __shared__ float A1r[4][5][5][KB], A1i[4][5][5][KB];   // 25.6 KB
    __shared__ float Mr [20][KB],      Mi [20][KB];        // 5.12 KB
    __shared__ float sLD;

    const int tid   = threadIdx.x;
    const int kbase = blockIdx.x * KB;

    if (tid == 0) sLD = 0.0f;
    __syncthreads();

    // ---- Phase A: per (k, j). tid<128: kl = tid&31, j = tid>>5 ----
    if (tid < 128) {
        const int kl = tid & 31;
        const int j  = tid >> 5;
        const int i1 = j*NK + kbase + kl;
        const int kg = kbase + kl;
        float A0r_[4], A0i_[4], T1r_[4], T1i_[4];
        float m1r = 0.f, m1i = 0.f, ld = 0.f;
        #pragma unroll
        for (int j0 = 0; j0 < 4; j0++) {
            const int i0 = j0*65536 + i1;
            float ar = l00r[i0], ai = l00i[i0];
            float br = l01r[i0], bi = l01i[i0];
            float n  = ar*ar + ai*ai;
            float d  = __fdividef(1.0f, n);
            float inr = ar*d, ini = -ai*d;
            A0r_[j0] = inr; A0i_[j0] = ini;
            float tr = br*inr - bi*ini, ti = br*ini + bi*inr;
            T1r_[j0] = tr; T1i_[j0] = ti;
            m1r += br*tr + bi*ti;
            m1i += br*ti - bi*tr;
            ld  += 0.5f*__logf(n);
        }
        float s1r = l11r[i1] - m1r, s1i = l11i[i1] - m1i;
        float n1 = s1r*s1r + s1i*s1i;
        ld += 0.5f*__logf(n1);
        float d1 = __fdividef(1.0f, n1);
        float isr = s1r*d1, isi = -s1i*d1;
        g_S1r[j*NK + kg] = isr;  g_S1i[j*NK + kg] = isi;
        #pragma unroll
        for (int a = 0; a < 4; a++) {
            float p1r = T1r_[a]*isr - T1i_[a]*isi;   // P1[a]
            float p1i = T1r_[a]*isi + T1i_[a]*isr;
            g_T1r[(j*4+a)*NK + kg] = T1r_[a];  g_T1i[(j*4+a)*NK + kg] = T1i_[a];
            g_P1r[(j*4+a)*NK + kg] = p1r;      g_P1i[(j*4+a)*NK + kg] = p1i;
            g_A0r[(j*4+a)*NK + kg] = A0r_[a];  g_A0i[(j*4+a)*NK + kg] = A0i_[a];
            #pragma unroll
            for (int b = 0; b < 4; b++) {
                float vr = p1r*T1r_[b] + p1i*T1i_[b];   // P1[a]*conj(T1[b])
                float vi = p1i*T1r_[b] - p1r*T1i_[b];
                if (a == b) { vr += A0r_[a]; vi += A0i_[a]; }
                A1r[j][a][b][kl] = vr; A1i[j][a][b][kl] = vi;
            }
            A1r[j][a][4][kl] = -p1r; A1i[j][a][4][kl] = -p1i;
            A1r[j][4][a][kl] = -p1r; A1i[j][4][a][kl] =  p1i;   // -conj(P1)
        }
        A1r[j][4][4][kl] = isr; A1i[j][4][4][kl] = isi;
        atomicAdd(&sLD, ld);
    }
    __syncthreads();

    // ---- Phase B: T2 rows. all 320 threads: row = tid>>4, pair k2 ----
    {
        const int row = tid >> 4;           // 0..19
        const int k2  = (tid & 15) * 2;
        const int a = row >> 2, j = row & 3;
        float tr0=0.f, ti0=0.f, tr1=0.f, ti1=0.f;
        float Byr0=0.f, Byi0=0.f, Byr1=0.f, Byi1=0.f;
        #pragma unroll
        for (int b = 0; b < 5; b++) {
            const int r2 = b*4 + j;
            const float* pr = (r2 < 16) ? (l02r + r2*NK) : (l12r + (r2-16)*NK);
            const float* pi = (r2 < 16) ? (l02i + r2*NK) : (l12i + (r2-16)*NK);
            float2 br = *(const float2*)(pr + kbase + k2);
            float2 bi = *(const float2*)(pi + kbase + k2);
            float2 Ar = *(float2*)&A1r[j][a][b][k2];
            float2 Ai = *(float2*)&A1i[j][a][b][k2];
            tr0 += br.x*Ar.x - bi.x*Ai.x;  ti0 += br.x*Ai.x + bi.x*Ar.x;
            tr1 += br.y*Ar.y - bi.y*Ai.y;  ti1 += br.y*Ai.y + bi.y*Ar.y;
            if (b == a) { Byr0 = br.x; Byi0 = bi.x; Byr1 = br.y; Byi1 = bi.y; }
        }
        *(float2*)&g_T2r[row*NK + kbase + k2] = make_float2(tr0, tr1);
        *(float2*)&g_T2i[row*NK + kbase + k2] = make_float2(ti0, ti1);
        // conj(By)*t
        *(float2*)&Mr[row][k2] = make_float2(Byr0*tr0 + Byi0*ti0, Byr1*tr1 + Byi1*ti1);
        *(float2*)&Mi[row][k2] = make_float2(Byr0*ti0 - Byi0*tr0, Byr1*ti1 - Byi1*tr1);
    }
    __syncthreads();

    // ---- S2: 32 threads, one per k ----
    if (tid < 32) {
        const int kl = tid;
        float mr = 0.f, mi = 0.f;
        #pragma unroll
        for (int p = 0; p < 20; p++) { mr += Mr[p][kl]; mi += Mi[p][kl]; }
        float sr = l22r[kbase + kl] - mr;
        float si = l22i[kbase + kl] - mi;
        float n  = sr*sr + si*si;
        float d  = __fdividef(1.0f, n);
        g_S2r[kbase + kl] = sr*d;
        g_S2i[kbase + kl] = -si*d;
        atomicAdd(&sLD, 0.5f*__logf(n));
    }
    __syncthreads();
    if (tid == 0) atomicAdd(&out[LOGDET_OFF], sLD);
}

// ================= K2: emit 21x21 blocks + zout (streaming) =================
__global__ __launch_bounds__(336, 3)
void _fmgp_k2(const float* __restrict__ zr, const float* __restrict__ zi,
              float* __restrict__ out)
{
    __shared__ float T2r[20][KB], T2i[20][KB];   // 5.12 KB
    __shared__ float Zr [21][KB], Zi [21][KB];   // 5.38 KB
    __shared__ float ISr[KB],     ISi[KB];       // 256 B

    const int tid   = threadIdx.x;
    const int kbase = blockIdx.x * KB;
    const int yy    = tid >> 4;        // row 0..20
    const int k2    = (tid & 15) * 2;  // k pair offset

    // stage z (all 336 threads), T2 (tid<320), iS2 (tid<32)
    *(float2*)&Zr[yy][k2] = *(const float2*)(zr + yy*NK + kbase + k2);
    *(float2*)&Zi[yy][k2] = *(const float2*)(zi + yy*NK + kbase + k2);
    if (tid < 320) {
        *(float2*)&T2r[yy][k2] = *(const float2*)&g_T2r[yy*NK + kbase + k2];
        *(float2*)&T2i[yy][k2] = *(const float2*)&g_T2i[yy*NK + kbase + k2];
    }
    if (tid < 32) { ISr[tid] = g_S2r[kbase + tid]; ISi[tid] = g_S2i[kbase + tid]; }

    // per-row A1 values -> registers (recomputed from compact state)
    const int pj = yy & 3, pa = yy >> 2;   // pa in 0..4 for yy<20
    float a1r0[5], a1i0[5], a1r1[5], a1i1[5];
    if (yy < 20) {
        const int base = pj*4*NK + kbase + k2;
        if (pa < 4) {
            float2 p1r = *(const float2*)&g_P1r[pa*NK + base];
            float2 p1i = *(const float2*)&g_P1i[pa*NK + base];
            float2 a0r = *(const float2*)&g_A0r[pa*NK + base];
            float2 a0i = *(const float2*)&g_A0i[pa*NK + base];
            #pragma unroll
            for (int b = 0; b < 4; b++) {
                float2 t1r = *(const float2*)&g_T1r[b*NK + base];
                float2 t1i = *(const float2*)&g_T1i[b*NK + base];
                a1r0[b] = p1r.x*t1r.x + p1i.x*t1i.x;   // P1*conj(T1[b])
                a1i0[b] = p1i.x*t1r.x - p1r.x*t1i.x;
                a1r1[b] = p1r.y*t1r.y + p1i.y*t1i.y;
                a1i1[b] = p1i.y*t1r.y - p1r.y*t1i.y;
                if (b == pa) { a1r0[b] += a0r.x; a1i0[b] += a0i.x;
                               a1r1[b] += a0r.y; a1i1[b] += a0i.y; }
            }
            a1r0[4] = -p1r.x; a1i0[4] = -p1i.x;
            a1r1[4] = -p1r.y; a1i1[4] = -p1i.y;
        } else {
            #pragma unroll
            for (int b = 0; b < 4; b++) {
                float2 p1r = *(const float2*)&g_P1r[b*NK + base];
                float2 p1i = *(const float2*)&g_P1i[b*NK + base];
                a1r0[b] = -p1r.x; a1i0[b] =  p1i.x;    // -conj(P1[b])
                a1r1[b] = -p1r.y; a1i1[b] =  p1i.y;
            }
            float2 s1r = *(const float2*)&g_S1r[pj*NK + kbase + k2];
            float2 s1i = *(const float2*)&g_S1i[pj*NK + kbase + k2];
            a1r0[4] = s1r.x; a1i0[4] = s1i.x;
            a1r1[4] = s1r.y; a1i1[4] = s1i.y;
        }
    }
    __syncthreads();

    const float2 isr2 = *(float2*)&ISr[k2];
    const float2 isi2 = *(float2*)&ISi[k2];
    float ur0=0.f, ui0=0.f, ur1=0.f, ui1=0.f;
    if (yy < 20) {
        float2 t_r = *(float2*)&T2r[yy][k2];
        float2 t_i = *(float2*)&T2i[yy][k2];
        ur0 = t_r.x*isr2.x - t_i.x*isi2.x;  ui0 = t_r.x*isi2.x + t_i.x*isr2.x;
        ur1 = t_r.y*isr2.y - t_i.y*isi2.y;  ui1 = t_r.y*isi2.y + t_i.y*isr2.y;
    }
    float za0r=0.f, za0i=0.f, za1r=0.f, za1i=0.f;
    float* outre = out + (yy*21)*NK + kbase + k2;
    float* outim = outre + A_ELEMS;
    #pragma unroll
    for (int q = 0; q < 21; q++) {
        float v0r, v0i, v1r, v1i;
        if (yy < 20) {
            if (q < 20) {
                float2 tqr = *(float2*)&T2r[q][k2];
                float2 tqi = *(float2*)&T2i[q][k2];
                v0r = ur0*tqr.x + ui0*tqi.x;  v0i = ui0*tqr.x - ur0*tqi.x;
                v1r = ur1*tqr.y + ui1*tqi.y;  v1i = ui1*tqr.y - ur1*tqi.y;
                if ((q & 3) == pj) {                     // A1 scatter (registers)
                    const int b = q >> 2;
                    v0r += a1r0[b]; v0i += a1i0[b];
                    v1r += a1r1[b]; v1i += a1i1[b];
                }
            } else {
                v0r = -ur0; v0i = -ui0; v1r = -ur1; v1i = -ui1;
            }
        } else {
            if (q < 20) {                                 // -conj(P2[q])
                float2 tqr = *(float2*)&T2r[q][k2];
                float2 tqi = *(float2*)&T2i[q][k2];
                float p0r = tqr.x*isr2.x - tqi.x*isi2.x;
                float p0i = tqr.x*isi2.x + tqi.x*isr2.x;
                float p1r = tqr.y*isr2.y - tqi.y*isi2.y;
                float p1i = tqr.y*isi2.y + tqi.y*isr2.y;
                v0r = -p0r; v0i = p0i; v1r = -p1r; v1i = p1i;
            } else {
                v0r = isr2.x; v0i = isi2.x; v1r = isr2.y; v1i = isi2.y;
            }
        }
        *(float2*)(outre + q*NK) = make_float2(v0r, v1r);
        *(float2*)(outim + q*NK) = make_float2(v0i, v1i);
        float2 zqr = *(float2*)&Zr[q][k2];
        float2 zqi = *(float2*)&Zi[q][k2];
        za0r += v0r*zqr.x - v0i*zqi.x;  za0i += v0r*zqi.x + v0i*zqr.x;
        za1r += v1r*zqr.y - v1i*zqi.y;  za1i += v1r*zqi.y + v1i*zqr.y;
    }
    // ZOUT base is odd -> 4B alignment only; scalar stores
    const int zb = yy*NK + kbase + k2;
    out[ZOUT_OFF + zb]            = za0r;
    out[ZOUT_OFF + zb + 1]        = za1r;
    out[ZOUT_OFF + ZTOT + zb]     = za0i;
    out[ZOUT_OFF + ZTOT + zb + 1] = za1i;
}

extern "C" void kernel_launch(void* const* d_in, const int* in_sizes, int n_in,
                              void* d_out, int out_size)
{
    const float* l00r = (const float*)d_in[0];
    const float* l00i = (const float*)d_in[1];
    const float* l01r = (const float*)d_in[2];
    const float* l01i = (const float*)d_in[3];
    const float* l02r = (const float*)d_in[4];
    const float* l02i = (const float*)d_in[5];
    const float* l11r = (const float*)d_in[6];
    const float* l11i = (const float*)d_in[7];
    const float* l12r = (const float*)d_in[8];
    const float* l12i = (const float*)d_in[9];
    const float* l22r = (const float*)d_in[10];
    const float* l22i = (const float*)d_in[11];
    const float* zr   = (const float*)d_in[12];
    const float* zi   = (const float*)d_in[13];
    float* out = (float*)d_out;

    _fmgp_zero_logdet<<<1, 1>>>(out);
    _fmgp_k1<<<NK / KB, 320>>>(l00r, l00i, l01r, l01i, l02r, l02i,
                               l11r, l11i, l12r, l12i, l22r, l22i, out);
    _fmgp_k2<<<NK / KB, 336>>>(zr, zi, out);
}

// round 10
// speedup vs baseline: 1.6913x; 1.6913x over previous
#include <cuda_runtime.h>

// Problem constants
#define NK 16384                 // finest block size N[2]
#define KB 32                    // k's per block
#define NBLK (NK / KB)           // 512 blocks
#define A_ELEMS (21*21*NK)       // 7225344 per (re/im) plane
#define LOGDET_OFF (2*A_ELEMS)   // 14450688
#define ZOUT_OFF (LOGDET_OFF+1)
#define ZTOT (21*NK)             // 344064

// logdet reduction scratch (device globals: allowed; zero-initialized at load)
__device__ float        g_ldpart[NBLK];
__device__ unsigned int g_ldcount = 0;

__global__ __launch_bounds__(336, 4)
void _fmgp_main(const float* __restrict__ l00r, const float* __restrict__ l00i,
                const float* __restrict__ l01r, const float* __restrict__ l01i,
                const float* __restrict__ l02r, const float* __restrict__ l02i,
                const float* __restrict__ l11r, const float* __restrict__ l11i,
                const float* __restrict__ l12r, const float* __restrict__ l12i,
                const float* __restrict__ l22r, const float* __restrict__ l22i,
                const float* __restrict__ zr,   const float* __restrict__ zi,
                float* __restrict__ out)
{
    __shared__ float A1r[4][5][5][KB], A1i[4][5][5][KB];   // 25.6 KB
    __shared__ float T2r[20][KB],      T2i[20][KB];        // 5.12 KB
    __shared__ float Zr [21][KB],      Zi [21][KB];        // 5.38 KB
    __shared__ float Mr [20][KB],      Mi [20][KB];        // 5.12 KB
    __shared__ float ISr[KB],          ISi[KB];            // 256 B
    __shared__ float sLD;

    const int tid   = threadIdx.x;
    const int kbase = blockIdx.x * KB;
    const int yy    = tid >> 4;        // row 0..20
    const int k2    = (tid & 15) * 2;  // k offset (pair) within block

    if (tid == 0) sLD = 0.0f;

    // ---- stage z (all 336 threads, float2) ----
    *(float2*)&Zr[yy][k2] = *(const float2*)(zr + yy*NK + kbase + k2);
    *(float2*)&Zi[yy][k2] = *(const float2*)(zi + yy*NK + kbase + k2);
    __syncthreads();

    // ---- Phase A: step-1 per (k, j). tid<128: kl = tid&31, j = tid>>5 ----
    if (tid < 128) {
        const int kl = tid & 31;
        const int j  = tid >> 5;
        const int i1 = j*NK + kbase + kl;
        float A0r_[4], A0i_[4], T1r_[4], T1i_[4];
        float m1r = 0.f, m1i = 0.f, ld = 0.f;
        #pragma unroll
        for (int j0 = 0; j0 < 4; j0++) {
            const int i0 = j0*65536 + i1;
            float ar = l00r[i0], ai = l00i[i0];
            float br = l01r[i0], bi = l01i[i0];
            float n  = ar*ar + ai*ai;
            float d  = __fdividef(1.0f, n);
            float inr = ar*d, ini = -ai*d;
            A0r_[j0] = inr; A0i_[j0] = ini;
            float tr = br*inr - bi*ini, ti = br*ini + bi*inr;
            T1r_[j0] = tr; T1i_[j0] = ti;
            m1r += br*tr + bi*ti;
            m1i += br*ti - bi*tr;
            ld  += 0.5f*__logf(n);
        }
        float s1r = l11r[i1] - m1r, s1i = l11i[i1] - m1i;
        float n1 = s1r*s1r + s1i*s1i;
        ld += 0.5f*__logf(n1);
        float d1 = __fdividef(1.0f, n1);
        float isr = s1r*d1, isi = -s1i*d1;
        #pragma unroll
        for (int a = 0; a < 4; a++) {
            float p1r = T1r_[a]*isr - T1i_[a]*isi;   // P1[a]
            float p1i = T1r_[a]*isi + T1i_[a]*isr;
            #pragma unroll
            for (int b = 0; b < 4; b++) {
                float vr = p1r*T1r_[b] + p1i*T1i_[b];   // P1[a]*conj(T1[b])
                float vi = p1i*T1r_[b] - p1r*T1i_[b];
                if (a == b) { vr += A0r_[a]; vi += A0i_[a]; }
                A1r[j][a][b][kl] = vr; A1i[j][a][b][kl] = vi;
            }
            A1r[j][a][4][kl] = -p1r; A1i[j][a][4][kl] = -p1i;
            A1r[j][4][a][kl] = -p1r; A1i[j][4][a][kl] =  p1i;   // -conj(P1)
        }
        A1r[j][4][4][kl] = isr; A1i[j][4][4][kl] = isi;
        atomicAdd(&sLD, ld);
    }
    __syncthreads();

    // ---- Phase B: T2 rows. tid<320: row = tid>>4 (p = a*4+j), pair k2 ----
    if (tid < 320) {
        const int row = yy;                 // 0..19
        const int a = row >> 2, j = row & 3;
        float tr0=0.f, ti0=0.f, tr1=0.f, ti1=0.f;
        float Byr0=0.f, Byi0=0.f, Byr1=0.f, Byi1=0.f;
        #pragma unroll
        for (int b = 0; b < 5; b++) {
            const int r2 = b*4 + j;
            const float* pr = (r2 < 16) ? (l02r + r2*NK) : (l12r + (r2-16)*NK);
            const float* pi = (r2 < 16) ? (l02i + r2*NK) : (l12i + (r2-16)*NK);
            float2 br = *(const float2*)(pr + kbase + k2);
            float2 bi = *(const float2*)(pi + kbase + k2);
            float2 Ar = *(float2*)&A1r[j][a][b][k2];
            float2 Ai = *(float2*)&A1i[j][a][b][k2];
            tr0 += br.x*Ar.x - bi.x*Ai.x;  ti0 += br.x*Ai.x + bi.x*Ar.x;
            tr1 += br.y*Ar.y - bi.y*Ai.y;  ti1 += br.y*Ai.y + bi.y*Ar.y;
            if (b == a) { Byr0 = br.x; Byi0 = bi.x; Byr1 = br.y; Byi1 = bi.y; }
        }
        *(float2*)&T2r[row][k2] = make_float2(tr0, tr1);
        *(float2*)&T2i[row][k2] = make_float2(ti0, ti1);
        // conj(By)*t
        *(float2*)&Mr[row][k2] = make_float2(Byr0*tr0 + Byi0*ti0, Byr1*tr1 + Byi1*ti1);
        *(float2*)&Mi[row][k2] = make_float2(Byr0*ti0 - Byi0*tr0, Byr1*ti1 - Byi1*tr1);
    }
    __syncthreads();

    // ---- S2: 32 threads, one per k (conflict-free scalar LDS) ----
    if (tid < 32) {
        const int kl = tid;
        float mr = 0.f, mi = 0.f;
        #pragma unroll
        for (int p = 0; p < 20; p++) { mr += Mr[p][kl]; mi += Mi[p][kl]; }
        float sr = l22r[kbase + kl] - mr;
        float si = l22i[kbase + kl] - mi;
        float n  = sr*sr + si*si;
        float d  = __fdividef(1.0f, n);
        ISr[kl] = sr*d; ISi[kl] = -si*d;
        atomicAdd(&sLD, 0.5f*__logf(n));
    }
    __syncthreads();

    // publish this block's logdet partial early (visibility fenced before the
    // end-of-kernel counter increment)
    if (tid == 0) g_ldpart[blockIdx.x] = sLD;

    // ---- Phase C: emit row yy of the 21x21 block + zout, 2 k per thread ----
    {
        const float2 isr2 = *(float2*)&ISr[k2];
        const float2 isi2 = *(float2*)&ISi[k2];
        float ur0=0.f, ui0=0.f, ur1=0.f, ui1=0.f;
        if (yy < 20) {
            float2 t_r = *(float2*)&T2r[yy][k2];
            float2 t_i = *(float2*)&T2i[yy][k2];
            ur0 = t_r.x*isr2.x - t_i.x*isi2.x;  ui0 = t_r.x*isi2.x + t_i.x*isr2.x;
            ur1 = t_r.y*isr2.y - t_i.y*isi2.y;  ui1 = t_r.y*isi2.y + t_i.y*isr2.y;
        }
        const int pj = yy & 3, pa = yy >> 2;
        float za0r=0.f, za0i=0.f, za1r=0.f, za1i=0.f;
        float* outre = out + (yy*21)*NK + kbase + k2;
        float* outim = outre + A_ELEMS;
        #pragma unroll
        for (int q = 0; q < 21; q++) {
            float v0r, v0i, v1r, v1i;
            if (yy < 20) {
                if (q < 20) {
                    float2 tqr = *(float2*)&T2r[q][k2];
                    float2 tqi = *(float2*)&T2i[q][k2];
                    v0r = ur0*tqr.x + ui0*tqi.x;  v0i = ui0*tqr.x - ur0*tqi.x;
                    v1r = ur1*tqr.y + ui1*tqi.y;  v1i = ui1*tqr.y - ur1*tqi.y;
                    if ((q & 3) == pj) {                     // A1_j scatter add
                        float2 ar = *(float2*)&A1r[pj][pa][q >> 2][k2];
                        float2 ai = *(float2*)&A1i[pj][pa][q >> 2][k2];
                        v0r += ar.x; v0i += ai.x; v1r += ar.y; v1i += ai.y;
                    }
                } else {
                    v0r = -ur0; v0i = -ui0; v1r = -ur1; v1i = -ui1;
                }
            } else {
                if (q < 20) {                                 // -conj(P2[q])
                    float2 tqr = *(float2*)&T2r[q][k2];
                    float2 tqi = *(float2*)&T2i[q][k2];
                    float p0r = tqr.x*isr2.x - tqi.x*isi2.x;
                    float p0i = tqr.x*isi2.x + tqi.x*isr2.x;
                    float p1r = tqr.y*isr2.y - tqi.y*isi2.y;
                    float p1i = tqr.y*isi2.y + tqi.y*isr2.y;
                    v0r = -p0r; v0i = p0i; v1r = -p1r; v1i = p1i;
                } else {
                    v0r = isr2.x; v0i = isi2.x; v1r = isr2.y; v1i = isi2.y;
                }
            }
            *(float2*)(outre + q*NK) = make_float2(v0r, v1r);
            *(float2*)(outim + q*NK) = make_float2(v0i, v1i);
            float2 zqr = *(float2*)&Zr[q][k2];
            float2 zqi = *(float2*)&Zi[q][k2];
            za0r += v0r*zqr.x - v0i*zqi.x;  za0i += v0r*zqi.x + v0i*zqr.x;
            za1r += v1r*zqr.y - v1i*zqi.y;  za1i += v1r*zqi.y + v1i*zqr.y;
        }
        // ZOUT base is odd -> 4B alignment only; scalar stores
        const int zb = yy*NK + kbase + k2;
        out[ZOUT_OFF + zb]            = za0r;
        out[ZOUT_OFF + zb + 1]        = za1r;
        out[ZOUT_OFF + ZTOT + zb]     = za0i;
        out[ZOUT_OFF + ZTOT + zb + 1] = za1i;
    }

    // ---- logdet finalize: last block reduces all partials ----
    if (tid < 32) {
        unsigned int old = 0;
        if (tid == 0) {
            __threadfence();                               // order g_ldpart store
            old = atomicInc(&g_ldcount, 0xFFFFFFFFu);
        }
        old = __shfl_sync(0xFFFFFFFFu, old, 0);
        if (old == NBLK - 1) {                             // last block
            __threadfence();                               // see all partials
            float s = 0.f;
            #pragma unroll
            for (int i = 0; i < NBLK / 32; i++) s += g_ldpart[tid + i*32];
            #pragma unroll
            for (int o = 16; o > 0; o >>= 1) s += __shfl_down_sync(0xFFFFFFFFu, s, o);
            if (tid == 0) {
                out[LOGDET_OFF] = s;
                g_ldcount = 0;                             // reset for next replay
            }
        }
    }
}

extern "C" void kernel_launch(void* const* d_in, const int* in_sizes, int n_in,
                              void* d_out, int out_size)
{
    const float* l00r = (const float*)d_in[0];
    const float* l00i = (const float*)d_in[1];
    const float* l01r = (const float*)d_in[2];
    const float* l01i = (const float*)d_in[3];
    const float* l02r = (const float*)d_in[4];
    const float* l02i = (const float*)d_in[5];
    const float* l11r = (const float*)d_in[6];
    const float* l11i = (const float*)d_in[7];
    const float* l12r = (const float*)d_in[8];
    const float* l12i = (const float*)d_in[9];
    const float* l22r = (const float*)d_in[10];
    const float* l22i = (const float*)d_in[11];
    const float* zr   = (const float*)d_in[12];
    const float* zi   = (const float*)d_in[13];
    float* out = (float*)d_out;

    _fmgp_main<<<NBLK, 336>>>(l00r, l00i, l01r, l01i, l02r, l02i,
                              l11r, l11i, l12r, l12i, l22r, l22i,
                              zr, zi, out);
}